// round 1
// baseline (speedup 1.0000x reference)
#include <cuda_runtime.h>

#define N_NODES 50000
#define N_EDGES 800000
#define EAUG    (N_EDGES + N_NODES)
#define HID     128
#define NCLS    40

// ---------------- scratch (static device globals; no runtime alloc) --------
__device__ float d_h0 [N_NODES * HID];
__device__ float d_x1 [N_NODES * HID];
__device__ float d_tmp[N_NODES * HID];
__device__ float d_G  [(size_t)N_NODES * 512];   // [xg | xcon | xdis | xself]
__device__ float d_s  [EAUG];
__device__ float d_Z  [2 * N_NODES];             // Zcon | Zdis (then reciprocals)
__device__ float d_stats[2 * HID];               // col sums | col sumsq
__device__ int   d_off [N_NODES + 1];
__device__ int   d_cur [N_NODES];
__device__ int   d_cnt [N_NODES];
__device__ int   d_eid [EAUG];

// ---------------- GEMM: C[i,j] = sum_k A[i,k]*B[j,k] (+bias), K=128 --------
struct GemmParts {
    const float* B[4];
    const float* bias[4];
    int ncols[4];
};

__global__ void __launch_bounds__(256) gemm_nt(
    const float* __restrict__ A, int nrows,
    GemmParts parts, float* __restrict__ C, int ldc)
{
    const int by = blockIdx.y;
    const float* __restrict__ B    = parts.B[by];
    const float* __restrict__ bias = parts.bias[by];
    const int ncols = parts.ncols[by];
    const int row0  = blockIdx.x * 128;

    __shared__ float As[16][128];
    __shared__ float Bs[16][128];

    const int t  = threadIdx.x;
    const int tx = t & 15;
    const int ty = t >> 4;

    float acc[8][8];
#pragma unroll
    for (int y = 0; y < 8; y++)
#pragma unroll
        for (int x = 0; x < 8; x++) acc[y][x] = 0.f;

    for (int k0 = 0; k0 < 128; k0 += 16) {
#pragma unroll
        for (int i = 0; i < 2; i++) {
            int lin = t + i * 256;
            int r   = lin >> 2;
            int kq  = lin & 3;
            float4 v = make_float4(0.f, 0.f, 0.f, 0.f);
            int grow = row0 + r;
            if (grow < nrows)
                v = *(const float4*)(A + (size_t)grow * 128 + k0 + kq * 4);
            As[kq * 4 + 0][r] = v.x;
            As[kq * 4 + 1][r] = v.y;
            As[kq * 4 + 2][r] = v.z;
            As[kq * 4 + 3][r] = v.w;
        }
#pragma unroll
        for (int i = 0; i < 2; i++) {
            int lin = t + i * 256;
            int j   = lin >> 2;
            int kq  = lin & 3;
            float4 v = make_float4(0.f, 0.f, 0.f, 0.f);
            if (j < ncols)
                v = *(const float4*)(B + (size_t)j * 128 + k0 + kq * 4);
            Bs[kq * 4 + 0][j] = v.x;
            Bs[kq * 4 + 1][j] = v.y;
            Bs[kq * 4 + 2][j] = v.z;
            Bs[kq * 4 + 3][j] = v.w;
        }
        __syncthreads();
#pragma unroll
        for (int kk = 0; kk < 16; kk++) {
            float a[8], b[8];
            *(float4*)&a[0] = *(const float4*)&As[kk][ty * 8];
            *(float4*)&a[4] = *(const float4*)&As[kk][ty * 8 + 4];
            *(float4*)&b[0] = *(const float4*)&Bs[kk][tx * 8];
            *(float4*)&b[4] = *(const float4*)&Bs[kk][tx * 8 + 4];
#pragma unroll
            for (int y = 0; y < 8; y++)
#pragma unroll
                for (int x = 0; x < 8; x++)
                    acc[y][x] = fmaf(a[y], b[x], acc[y][x]);
        }
        __syncthreads();
    }

#pragma unroll
    for (int y = 0; y < 8; y++) {
        int grow = row0 + ty * 8 + y;
        if (grow >= nrows) continue;
        float* cp = C + (size_t)grow * ldc + by * 128;
#pragma unroll
        for (int xq = 0; xq < 2; xq++) {
            int col = tx * 8 + xq * 4;
            if (col >= ncols) continue;
            float4 v;
            v.x = acc[y][xq * 4 + 0];
            v.y = acc[y][xq * 4 + 1];
            v.z = acc[y][xq * 4 + 2];
            v.w = acc[y][xq * 4 + 3];
            if (bias) {
                v.x += bias[col + 0];
                v.y += bias[col + 1];
                v.z += bias[col + 2];
                v.w += bias[col + 3];
            }
            *(float4*)(cp + col) = v;
        }
    }
}

// ---------------- BatchNorm --------------------------------------------------
__global__ void bn_stats(const float* __restrict__ X, float* __restrict__ stats)
{
    int c  = threadIdx.x;
    int r0 = blockIdx.x * 256;
    int r1 = min(r0 + 256, N_NODES);
    float s = 0.f, q = 0.f;
    for (int r = r0; r < r1; r++) {
        float v = X[(size_t)r * 128 + c];
        s += v;
        q = fmaf(v, v, q);
    }
    atomicAdd(&stats[c], s);
    atomicAdd(&stats[128 + c], q);
}

__global__ void bn_apply(const float* __restrict__ X, const float* __restrict__ stats,
                         const float* __restrict__ gamma, const float* __restrict__ beta,
                         const float* __restrict__ residual, float* __restrict__ out)
{
    int i = blockIdx.x * blockDim.x + threadIdx.x;
    if (i >= N_NODES * 128) return;
    int c = i & 127;
    const float invN = 1.f / (float)N_NODES;
    float m   = stats[c] * invN;
    float var = stats[128 + c] * invN - m * m;
    float v = gamma[c] * (X[i] - m) * rsqrtf(var + 1e-5f) + beta[c];
    v = fmaxf(v, 0.f);
    if (residual) v += residual[i];
    out[i] = v;
}

// ---------------- small utility kernels -------------------------------------
__global__ void zero_f(float* __restrict__ p, int n)
{
    int i = blockIdx.x * blockDim.x + threadIdx.x;
    if (i < n) p[i] = 0.f;
}

__global__ void recip_f(float* __restrict__ p, int n)
{
    int i = blockIdx.x * blockDim.x + threadIdx.x;
    if (i < n) p[i] = 1.f / p[i];
}

__global__ void init_counts_k(int* __restrict__ cnt)
{
    int i = blockIdx.x * blockDim.x + threadIdx.x;
    if (i < N_NODES) cnt[i] = 1;   // self loop
}

__global__ void hist_k(const int* __restrict__ ei1, int* __restrict__ cnt)
{
    int e = blockIdx.x * blockDim.x + threadIdx.x;
    if (e < N_EDGES) atomicAdd(&cnt[ei1[e]], 1);
}

__global__ void scan_k(const int* __restrict__ cnt, int* __restrict__ off,
                       int* __restrict__ cur)
{
    __shared__ int sh[1024];
    const int CH = (N_NODES + 1023) / 1024;
    int t = threadIdx.x;
    int base = t * CH;
    int local = 0;
    for (int i = 0; i < CH; i++) {
        int idx = base + i;
        if (idx < N_NODES) local += cnt[idx];
    }
    sh[t] = local;
    __syncthreads();
    for (int o = 1; o < 1024; o <<= 1) {
        int v = 0;
        if (t >= o) v = sh[t - o];
        __syncthreads();
        if (t >= o) sh[t] += v;
        __syncthreads();
    }
    int run = (t == 0) ? 0 : sh[t - 1];
    for (int i = 0; i < CH; i++) {
        int idx = base + i;
        if (idx < N_NODES) {
            off[idx] = run;
            cur[idx] = run;
            run += cnt[idx];
        }
    }
    if (t == 0) off[N_NODES] = EAUG;
}

__global__ void csr_fill_k(const int* __restrict__ ei1, int* __restrict__ cur,
                           int* __restrict__ eid)
{
    int e = blockIdx.x * blockDim.x + threadIdx.x;
    if (e >= EAUG) return;
    int c = (e < N_EDGES) ? ei1[e] : (e - N_EDGES);
    int pos = atomicAdd(&cur[c], 1);
    eid[pos] = e;
}

// ---------------- edge pass 1: per-edge score s, row-group Z sums ------------
__global__ void edge_pass1(const float* __restrict__ G,
                           const int* __restrict__ ei0, const int* __restrict__ ei1,
                           const float* __restrict__ Wh, const float* __restrict__ bh,
                           float* __restrict__ s_buf, float* __restrict__ Z)
{
    int gw   = (blockIdx.x * blockDim.x + threadIdx.x) >> 5;
    int lane = threadIdx.x & 31;
    if (gw >= EAUG) return;
    int r, c;
    if (gw < N_EDGES) { r = ei0[gw]; c = ei1[gw]; }
    else              { r = gw - N_EDGES; c = r; }

    float4 xr = ((const float4*)(G + (size_t)r * 512))[lane];
    float4 xc = ((const float4*)(G + (size_t)c * 512))[lane];
    float4 a  = ((const float4*)Wh)[lane];
    float4 b  = ((const float4*)Wh)[lane + 32];

    float dx = xr.x - xc.x, dy = xr.y - xc.y, dz = xr.z - xc.z, dw = xr.w - xc.w;
    float ss = dx * dx + dy * dy + dz * dz + dw * dw;
    float dp = xr.x * a.x + xr.y * a.y + xr.z * a.z + xr.w * a.w
             + xc.x * b.x + xc.y * b.y + xc.z * b.z + xc.w * b.w;
#pragma unroll
    for (int o = 16; o > 0; o >>= 1) {
        ss += __shfl_xor_sync(0xffffffffu, ss, o);
        dp += __shfl_xor_sync(0xffffffffu, dp, o);
    }
    if (lane == 0) {
        float g = sqrtf(ss + 1e-12f);
        float t = dp + bh[0];
        float h = fmaxf(t, 0.f) + log1pf(__expf(-fabsf(t)));   // softplus
        float s = 1.f / (1.f + __expf(g + h));                 // sigmoid(-(g+h))
        s_buf[gw] = s;
        atomicAdd(&Z[r],           __expf(s));
        atomicAdd(&Z[N_NODES + r], __expf(1.f - s));
    }
}

// ---------------- aggregation (CSR by col) + gate softmax + residual --------
__global__ void agg_gate(const float* __restrict__ G,
                         const int* __restrict__ off, const int* __restrict__ eid,
                         const int* __restrict__ ei0,
                         const float* __restrict__ s_buf, const float* __restrict__ invZ,
                         const float* __restrict__ Wgate, const float* __restrict__ bgate,
                         const float* __restrict__ residual, float* __restrict__ out)
{
    int node = (blockIdx.x * blockDim.x + threadIdx.x) >> 5;
    int lane = threadIdx.x & 31;
    if (node >= N_NODES) return;

    int p0 = off[node], p1 = off[node + 1];
    float4 ac = make_float4(0.f, 0.f, 0.f, 0.f);
    float4 ad = make_float4(0.f, 0.f, 0.f, 0.f);
    for (int p = p0; p < p1; p++) {
        int e = eid[p];
        int r = (e < N_EDGES) ? ei0[e] : (e - N_EDGES);
        float s  = s_buf[e];
        float wc = __expf(s)       * invZ[r];
        float wd = __expf(1.f - s) * invZ[N_NODES + r];
        float4 vc = ((const float4*)(G + (size_t)r * 512 + 128))[lane];
        float4 vd = ((const float4*)(G + (size_t)r * 512 + 256))[lane];
        ac.x = fmaf(wc, vc.x, ac.x); ac.y = fmaf(wc, vc.y, ac.y);
        ac.z = fmaf(wc, vc.z, ac.z); ac.w = fmaf(wc, vc.w, ac.w);
        ad.x = fmaf(wd, vd.x, ad.x); ad.y = fmaf(wd, vd.y, ad.y);
        ad.z = fmaf(wd, vd.z, ad.z); ad.w = fmaf(wd, vd.w, ad.w);
    }
    float4 sf = ((const float4*)(G + (size_t)node * 512 + 384))[lane];

    float l[3];
#pragma unroll
    for (int k = 0; k < 3; k++) {
        float4 w0 = ((const float4*)(Wgate + k * 384))[lane];
        float4 w1 = ((const float4*)(Wgate + k * 384 + 128))[lane];
        float4 w2 = ((const float4*)(Wgate + k * 384 + 256))[lane];
        l[k] = w0.x * ac.x + w0.y * ac.y + w0.z * ac.z + w0.w * ac.w
             + w1.x * ad.x + w1.y * ad.y + w1.z * ad.z + w1.w * ad.w
             + w2.x * sf.x + w2.y * sf.y + w2.z * sf.z + w2.w * sf.w;
    }
#pragma unroll
    for (int o = 16; o > 0; o >>= 1) {
        l[0] += __shfl_xor_sync(0xffffffffu, l[0], o);
        l[1] += __shfl_xor_sync(0xffffffffu, l[1], o);
        l[2] += __shfl_xor_sync(0xffffffffu, l[2], o);
    }
    l[0] += bgate[0]; l[1] += bgate[1]; l[2] += bgate[2];
    float m  = fmaxf(l[0], fmaxf(l[1], l[2]));
    float e0 = __expf(l[0] - m), e1 = __expf(l[1] - m), e2 = __expf(l[2] - m);
    float inv = 1.f / (e0 + e1 + e2);
    float g0 = e0 * inv, g1 = e1 * inv, g2 = e2 * inv;

    float4 o4;
    o4.x = g0 * ac.x + g1 * ad.x + g2 * sf.x;
    o4.y = g0 * ac.y + g1 * ad.y + g2 * sf.y;
    o4.z = g0 * ac.z + g1 * ad.z + g2 * sf.z;
    o4.w = g0 * ac.w + g1 * ad.w + g2 * sf.w;
    if (residual) {
        float4 rv = ((const float4*)(residual + (size_t)node * 128))[lane];
        o4.x += rv.x; o4.y += rv.y; o4.z += rv.z; o4.w += rv.w;
    }
    ((float4*)(out + (size_t)node * 128))[lane] = o4;
}

// ---------------- launch ------------------------------------------------------
extern "C" void kernel_launch(void* const* d_in, const int* in_sizes, int n_in,
                              void* d_out, int out_size)
{
    (void)in_sizes; (void)n_in; (void)out_size;
    const float* x       = (const float*)d_in[0];
    const int*   ei      = (const int*)d_in[1];
    const float* mlp_W   = (const float*)d_in[2];
    const float* mlp_b   = (const float*)d_in[3];
    const float* mlp_g   = (const float*)d_in[4];
    const float* mlp_be  = (const float*)d_in[5];
    const float* bn0_g   = (const float*)d_in[6];
    const float* bn0_be  = (const float*)d_in[7];
    const float* cls_W   = (const float*)d_in[8];
    const float* cls_b   = (const float*)d_in[9];
    const float* Wg[2]    = {(const float*)d_in[10], (const float*)d_in[19]};
    const float* Wh[2]    = {(const float*)d_in[11], (const float*)d_in[20]};
    const float* bh[2]    = {(const float*)d_in[12], (const float*)d_in[21]};
    const float* Wcon[2]  = {(const float*)d_in[13], (const float*)d_in[22]};
    const float* Wdis[2]  = {(const float*)d_in[14], (const float*)d_in[23]};
    const float* Wself[2] = {(const float*)d_in[15], (const float*)d_in[24]};
    const float* bself[2] = {(const float*)d_in[16], (const float*)d_in[25]};
    const float* Wgate[2] = {(const float*)d_in[17], (const float*)d_in[26]};
    const float* bgate[2] = {(const float*)d_in[18], (const float*)d_in[27]};
    const int* ei0 = ei;
    const int* ei1 = ei + N_EDGES;
    float* out = (float*)d_out;

    float *pH0, *pX1, *pTmp, *pG, *pS, *pZ, *pStats;
    int *pOff, *pCur, *pCnt, *pEid;
    cudaGetSymbolAddress((void**)&pH0,   d_h0);
    cudaGetSymbolAddress((void**)&pX1,   d_x1);
    cudaGetSymbolAddress((void**)&pTmp,  d_tmp);
    cudaGetSymbolAddress((void**)&pG,    d_G);
    cudaGetSymbolAddress((void**)&pS,    d_s);
    cudaGetSymbolAddress((void**)&pZ,    d_Z);
    cudaGetSymbolAddress((void**)&pStats,d_stats);
    cudaGetSymbolAddress((void**)&pOff,  d_off);
    cudaGetSymbolAddress((void**)&pCur,  d_cur);
    cudaGetSymbolAddress((void**)&pCnt,  d_cnt);
    cudaGetSymbolAddress((void**)&pEid,  d_eid);

    const int GR = (N_NODES + 127) / 128;          // 391 row blocks

    // ---- MLP + BN + relu -> h0
    {
        GemmParts gp = {};
        gp.B[0] = mlp_W; gp.bias[0] = mlp_b; gp.ncols[0] = 128;
        gemm_nt<<<dim3(GR, 1), 256>>>(x, N_NODES, gp, pTmp, 128);
    }
    zero_f<<<1, 256>>>(pStats, 256);
    bn_stats<<<(N_NODES + 255) / 256, 128>>>(pTmp, pStats);
    bn_apply<<<(N_NODES * 128 + 255) / 256, 256>>>(pTmp, pStats, mlp_g, mlp_be,
                                                   nullptr, pH0);

    // ---- CSR by col (shared by both layers)
    init_counts_k<<<(N_NODES + 255) / 256, 256>>>(pCnt);
    hist_k<<<(N_EDGES + 255) / 256, 256>>>(ei1, pCnt);
    scan_k<<<1, 1024>>>(pCnt, pOff, pCur);
    csr_fill_k<<<(EAUG + 255) / 256, 256>>>(ei1, pCur, pEid);

    // ---- conv layers
    const float* lin[2] = {pH0, pX1};
    for (int l = 0; l < 2; l++) {
        GemmParts gp = {};
        gp.B[0] = Wg[l];   gp.ncols[0] = 128;
        gp.B[1] = Wcon[l]; gp.ncols[1] = 128;
        gp.B[2] = Wdis[l]; gp.ncols[2] = 128;
        gp.B[3] = Wself[l]; gp.bias[3] = bself[l]; gp.ncols[3] = 128;
        gemm_nt<<<dim3(GR, 4), 256>>>(lin[l], N_NODES, gp, pG, 512);

        zero_f<<<(2 * N_NODES + 255) / 256, 256>>>(pZ, 2 * N_NODES);
        edge_pass1<<<(EAUG * 32 + 255) / 256, 256>>>(pG, ei0, ei1, Wh[l], bh[l],
                                                     pS, pZ);
        recip_f<<<(2 * N_NODES + 255) / 256, 256>>>(pZ, 2 * N_NODES);
        agg_gate<<<(N_NODES * 32 + 255) / 256, 256>>>(pG, pOff, pEid, ei0, pS, pZ,
                                                      Wgate[l], bgate[l],
                                                      (l == 0) ? nullptr : pX1,
                                                      pTmp);
        if (l == 0) {
            zero_f<<<1, 256>>>(pStats, 256);
            bn_stats<<<(N_NODES + 255) / 256, 128>>>(pTmp, pStats);
            bn_apply<<<(N_NODES * 128 + 255) / 256, 256>>>(pTmp, pStats, bn0_g,
                                                           bn0_be, pH0, pX1);
        }
    }

    // ---- classifier: out = x2 @ cls_W.T + cls_b   (x2 lives in d_tmp)
    {
        GemmParts gp = {};
        gp.B[0] = cls_W; gp.bias[0] = cls_b; gp.ncols[0] = 40;
        gemm_nt<<<dim3(GR, 1), 256>>>(pTmp, N_NODES, gp, out, 40);
    }
}

// round 2
// speedup vs baseline: 1.0476x; 1.0476x over previous
#include <cuda_runtime.h>

#define N_NODES 50000
#define N_EDGES 800000
#define EAUG    (N_EDGES + N_NODES)
#define HID     128
#define NCLS    40

// ---------------- scratch (static device globals; no runtime alloc) --------
__device__ float d_h0 [N_NODES * HID];
__device__ float d_x1 [N_NODES * HID];
__device__ float d_tmp[N_NODES * HID];
__device__ float d_G  [(size_t)N_NODES * 512];   // [xg | xcon | xdis | xself]
__device__ float d_s  [EAUG];
__device__ float d_Z  [2 * N_NODES];             // Zcon | Zdis (then reciprocals)
__device__ float d_stats[2 * HID];               // col sums | col sumsq
__device__ int   d_off [N_NODES + 1];
__device__ int   d_cur [N_NODES];
__device__ int   d_cnt [N_NODES];
__device__ int   d_eid [EAUG];

// ---------------- GEMM: C[i,j] = sum_k A[i,k]*B[j,k] (+bias), K=128 --------
// Packed fp32x2 FMA version: 8x8 micro-tile held as 8x4 f32x2 accumulators.
struct GemmParts {
    const float* B[4];
    const float* bias[4];
    int ncols[4];
};

__device__ __forceinline__ unsigned long long pack_dup(float a) {
    unsigned long long r;
    asm("mov.b64 %0, {%1, %1};" : "=l"(r) : "f"(a));
    return r;
}
__device__ __forceinline__ unsigned long long pack2(float lo, float hi) {
    unsigned long long r;
    asm("mov.b64 %0, {%1, %2};" : "=l"(r) : "f"(lo), "f"(hi));
    return r;
}
__device__ __forceinline__ void fma2(unsigned long long& d,
                                     unsigned long long a, unsigned long long b) {
    asm("fma.rn.f32x2 %0, %1, %2, %0;" : "+l"(d) : "l"(a), "l"(b));
}
__device__ __forceinline__ void unpack2(unsigned long long v, float& lo, float& hi) {
    asm("mov.b64 {%0, %1}, %2;" : "=f"(lo), "=f"(hi) : "l"(v));
}

__global__ void __launch_bounds__(256) gemm_nt(
    const float* __restrict__ A, int nrows,
    GemmParts parts, float* __restrict__ C, int ldc)
{
    const int by = blockIdx.y;
    const float* __restrict__ B    = parts.B[by];
    const float* __restrict__ bias = parts.bias[by];
    const int ncols = parts.ncols[by];
    const int row0  = blockIdx.x * 128;

    __shared__ float As[16][128];
    __shared__ float Bs[16][128];

    const int t  = threadIdx.x;
    const int tx = t & 15;
    const int ty = t >> 4;

    unsigned long long acc[8][4];
#pragma unroll
    for (int y = 0; y < 8; y++)
#pragma unroll
        for (int x = 0; x < 4; x++) acc[y][x] = 0ULL;

    for (int k0 = 0; k0 < 128; k0 += 16) {
#pragma unroll
        for (int i = 0; i < 2; i++) {
            int lin = t + i * 256;
            int r   = lin >> 2;
            int kq  = lin & 3;
            float4 v = make_float4(0.f, 0.f, 0.f, 0.f);
            int grow = row0 + r;
            if (grow < nrows)
                v = *(const float4*)(A + (size_t)grow * 128 + k0 + kq * 4);
            As[kq * 4 + 0][r] = v.x;
            As[kq * 4 + 1][r] = v.y;
            As[kq * 4 + 2][r] = v.z;
            As[kq * 4 + 3][r] = v.w;
        }
#pragma unroll
        for (int i = 0; i < 2; i++) {
            int lin = t + i * 256;
            int j   = lin >> 2;
            int kq  = lin & 3;
            float4 v = make_float4(0.f, 0.f, 0.f, 0.f);
            if (j < ncols)
                v = *(const float4*)(B + (size_t)j * 128 + k0 + kq * 4);
            Bs[kq * 4 + 0][j] = v.x;
            Bs[kq * 4 + 1][j] = v.y;
            Bs[kq * 4 + 2][j] = v.z;
            Bs[kq * 4 + 3][j] = v.w;
        }
        __syncthreads();
#pragma unroll
        for (int kk = 0; kk < 16; kk++) {
            float a[8], b[8];
            *(float4*)&a[0] = *(const float4*)&As[kk][ty * 8];
            *(float4*)&a[4] = *(const float4*)&As[kk][ty * 8 + 4];
            *(float4*)&b[0] = *(const float4*)&Bs[kk][tx * 8];
            *(float4*)&b[4] = *(const float4*)&Bs[kk][tx * 8 + 4];
            unsigned long long ad[8], b2[4];
#pragma unroll
            for (int y = 0; y < 8; y++) ad[y] = pack_dup(a[y]);
#pragma unroll
            for (int x = 0; x < 4; x++) b2[x] = pack2(b[2 * x], b[2 * x + 1]);
#pragma unroll
            for (int y = 0; y < 8; y++)
#pragma unroll
                for (int x = 0; x < 4; x++)
                    fma2(acc[y][x], ad[y], b2[x]);
        }
        __syncthreads();
    }

#pragma unroll
    for (int y = 0; y < 8; y++) {
        int grow = row0 + ty * 8 + y;
        if (grow >= nrows) continue;
        float* cp = C + (size_t)grow * ldc + by * 128;
#pragma unroll
        for (int xq = 0; xq < 2; xq++) {
            int col = tx * 8 + xq * 4;
            if (col >= ncols) continue;
            float4 v;
            unpack2(acc[y][xq * 2 + 0], v.x, v.y);
            unpack2(acc[y][xq * 2 + 1], v.z, v.w);
            if (bias) {
                v.x += bias[col + 0];
                v.y += bias[col + 1];
                v.z += bias[col + 2];
                v.w += bias[col + 3];
            }
            *(float4*)(cp + col) = v;
        }
    }
}

// ---------------- BatchNorm --------------------------------------------------
__global__ void bn_stats(const float* __restrict__ X, float* __restrict__ stats)
{
    int c  = threadIdx.x;
    int r0 = blockIdx.x * 256;
    int r1 = min(r0 + 256, N_NODES);
    float s = 0.f, q = 0.f;
    for (int r = r0; r < r1; r++) {
        float v = X[(size_t)r * 128 + c];
        s += v;
        q = fmaf(v, v, q);
    }
    atomicAdd(&stats[c], s);
    atomicAdd(&stats[128 + c], q);
}

__global__ void bn_apply(const float4* __restrict__ X, const float* __restrict__ stats,
                         const float* __restrict__ gamma, const float* __restrict__ beta,
                         const float4* __restrict__ residual, float4* __restrict__ out)
{
    int i = blockIdx.x * blockDim.x + threadIdx.x;
    if (i >= N_NODES * 32) return;
    int c0 = (i & 31) * 4;
    const float invN = 1.f / (float)N_NODES;
    float4 v = X[i];
    float r[4] = {v.x, v.y, v.z, v.w};
#pragma unroll
    for (int k = 0; k < 4; k++) {
        int c = c0 + k;
        float m   = stats[c] * invN;
        float var = stats[128 + c] * invN - m * m;
        float u = gamma[c] * (r[k] - m) * rsqrtf(var + 1e-5f) + beta[c];
        r[k] = fmaxf(u, 0.f);
    }
    float4 o = make_float4(r[0], r[1], r[2], r[3]);
    if (residual) {
        float4 rv = residual[i];
        o.x += rv.x; o.y += rv.y; o.z += rv.z; o.w += rv.w;
    }
    out[i] = o;
}

// ---------------- small utility kernels -------------------------------------
__global__ void zero_f(float* __restrict__ p, int n)
{
    int i = blockIdx.x * blockDim.x + threadIdx.x;
    if (i < n) p[i] = 0.f;
}

__global__ void recip_f(float* __restrict__ p, int n)
{
    int i = blockIdx.x * blockDim.x + threadIdx.x;
    if (i < n) p[i] = 1.f / p[i];
}

__global__ void init_counts_k(int* __restrict__ cnt)
{
    int i = blockIdx.x * blockDim.x + threadIdx.x;
    if (i < N_NODES) cnt[i] = 1;   // self loop
}

__global__ void hist_k(const int* __restrict__ ei1, int* __restrict__ cnt)
{
    int e = blockIdx.x * blockDim.x + threadIdx.x;
    if (e < N_EDGES) atomicAdd(&cnt[ei1[e]], 1);
}

__global__ void scan_k(const int* __restrict__ cnt, int* __restrict__ off,
                       int* __restrict__ cur)
{
    __shared__ int sh[1024];
    const int CH = (N_NODES + 1023) / 1024;
    int t = threadIdx.x;
    int base = t * CH;
    int local = 0;
    for (int i = 0; i < CH; i++) {
        int idx = base + i;
        if (idx < N_NODES) local += cnt[idx];
    }
    sh[t] = local;
    __syncthreads();
    for (int o = 1; o < 1024; o <<= 1) {
        int v = 0;
        if (t >= o) v = sh[t - o];
        __syncthreads();
        if (t >= o) sh[t] += v;
        __syncthreads();
    }
    int run = (t == 0) ? 0 : sh[t - 1];
    for (int i = 0; i < CH; i++) {
        int idx = base + i;
        if (idx < N_NODES) {
            off[idx] = run;
            cur[idx] = run;
            run += cnt[idx];
        }
    }
    if (t == 0) off[N_NODES] = EAUG;
}

__global__ void csr_fill_k(const int* __restrict__ ei1, int* __restrict__ cur,
                           int* __restrict__ eid)
{
    int e = blockIdx.x * blockDim.x + threadIdx.x;
    if (e >= EAUG) return;
    int c = (e < N_EDGES) ? ei1[e] : (e - N_EDGES);
    int pos = atomicAdd(&cur[c], 1);
    eid[pos] = e;
}

// ---------------- edge pass 1: per-edge score s, row-group Z sums ------------
__global__ void edge_pass1(const float* __restrict__ G,
                           const int* __restrict__ ei0, const int* __restrict__ ei1,
                           const float* __restrict__ Wh, const float* __restrict__ bh,
                           float* __restrict__ s_buf, float* __restrict__ Z)
{
    int gw   = (blockIdx.x * blockDim.x + threadIdx.x) >> 5;
    int lane = threadIdx.x & 31;
    if (gw >= EAUG) return;
    int r, c;
    if (gw < N_EDGES) { r = ei0[gw]; c = ei1[gw]; }
    else              { r = gw - N_EDGES; c = r; }

    float4 xr = ((const float4*)(G + (size_t)r * 512))[lane];
    float4 xc = ((const float4*)(G + (size_t)c * 512))[lane];
    float4 a  = ((const float4*)Wh)[lane];
    float4 b  = ((const float4*)Wh)[lane + 32];

    float dx = xr.x - xc.x, dy = xr.y - xc.y, dz = xr.z - xc.z, dw = xr.w - xc.w;
    float ss = dx * dx + dy * dy + dz * dz + dw * dw;
    float dp = xr.x * a.x + xr.y * a.y + xr.z * a.z + xr.w * a.w
             + xc.x * b.x + xc.y * b.y + xc.z * b.z + xc.w * b.w;
#pragma unroll
    for (int o = 16; o > 0; o >>= 1) {
        ss += __shfl_xor_sync(0xffffffffu, ss, o);
        dp += __shfl_xor_sync(0xffffffffu, dp, o);
    }
    if (lane == 0) {
        float g = sqrtf(ss + 1e-12f);
        float t = dp + bh[0];
        float h = fmaxf(t, 0.f) + log1pf(__expf(-fabsf(t)));   // softplus
        float s = 1.f / (1.f + __expf(g + h));                 // sigmoid(-(g+h))
        s_buf[gw] = s;
        atomicAdd(&Z[r],           __expf(s));
        atomicAdd(&Z[N_NODES + r], __expf(1.f - s));
    }
}

// ---------------- aggregation (CSR by col) + gate softmax + residual --------
__global__ void agg_gate(const float* __restrict__ G,
                         const int* __restrict__ off, const int* __restrict__ eid,
                         const int* __restrict__ ei0,
                         const float* __restrict__ s_buf, const float* __restrict__ invZ,
                         const float* __restrict__ Wgate, const float* __restrict__ bgate,
                         const float* __restrict__ residual, float* __restrict__ out)
{
    int node = (blockIdx.x * blockDim.x + threadIdx.x) >> 5;
    int lane = threadIdx.x & 31;
    if (node >= N_NODES) return;

    int p0 = off[node], p1 = off[node + 1];
    float4 ac = make_float4(0.f, 0.f, 0.f, 0.f);
    float4 ad = make_float4(0.f, 0.f, 0.f, 0.f);
    for (int p = p0; p < p1; p++) {
        int e = eid[p];
        int r = (e < N_EDGES) ? ei0[e] : (e - N_EDGES);
        float s  = s_buf[e];
        float wc = __expf(s)       * invZ[r];
        float wd = __expf(1.f - s) * invZ[N_NODES + r];
        float4 vc = ((const float4*)(G + (size_t)r * 512 + 128))[lane];
        float4 vd = ((const float4*)(G + (size_t)r * 512 + 256))[lane];
        ac.x = fmaf(wc, vc.x, ac.x); ac.y = fmaf(wc, vc.y, ac.y);
        ac.z = fmaf(wc, vc.z, ac.z); ac.w = fmaf(wc, vc.w, ac.w);
        ad.x = fmaf(wd, vd.x, ad.x); ad.y = fmaf(wd, vd.y, ad.y);
        ad.z = fmaf(wd, vd.z, ad.z); ad.w = fmaf(wd, vd.w, ad.w);
    }
    float4 sf = ((const float4*)(G + (size_t)node * 512 + 384))[lane];

    float l[3];
#pragma unroll
    for (int k = 0; k < 3; k++) {
        float4 w0 = ((const float4*)(Wgate + k * 384))[lane];
        float4 w1 = ((const float4*)(Wgate + k * 384 + 128))[lane];
        float4 w2 = ((const float4*)(Wgate + k * 384 + 256))[lane];
        l[k] = w0.x * ac.x + w0.y * ac.y + w0.z * ac.z + w0.w * ac.w
             + w1.x * ad.x + w1.y * ad.y + w1.z * ad.z + w1.w * ad.w
             + w2.x * sf.x + w2.y * sf.y + w2.z * sf.z + w2.w * sf.w;
    }
#pragma unroll
    for (int o = 16; o > 0; o >>= 1) {
        l[0] += __shfl_xor_sync(0xffffffffu, l[0], o);
        l[1] += __shfl_xor_sync(0xffffffffu, l[1], o);
        l[2] += __shfl_xor_sync(0xffffffffu, l[2], o);
    }
    l[0] += bgate[0]; l[1] += bgate[1]; l[2] += bgate[2];
    float m  = fmaxf(l[0], fmaxf(l[1], l[2]));
    float e0 = __expf(l[0] - m), e1 = __expf(l[1] - m), e2 = __expf(l[2] - m);
    float inv = 1.f / (e0 + e1 + e2);
    float g0 = e0 * inv, g1 = e1 * inv, g2 = e2 * inv;

    float4 o4;
    o4.x = g0 * ac.x + g1 * ad.x + g2 * sf.x;
    o4.y = g0 * ac.y + g1 * ad.y + g2 * sf.y;
    o4.z = g0 * ac.z + g1 * ad.z + g2 * sf.z;
    o4.w = g0 * ac.w + g1 * ad.w + g2 * sf.w;
    if (residual) {
        float4 rv = ((const float4*)(residual + (size_t)node * 128))[lane];
        o4.x += rv.x; o4.y += rv.y; o4.z += rv.z; o4.w += rv.w;
    }
    ((float4*)(out + (size_t)node * 128))[lane] = o4;
}

// ---------------- launch ------------------------------------------------------
extern "C" void kernel_launch(void* const* d_in, const int* in_sizes, int n_in,
                              void* d_out, int out_size)
{
    (void)in_sizes; (void)n_in; (void)out_size;
    const float* x       = (const float*)d_in[0];
    const int*   ei      = (const int*)d_in[1];
    const float* mlp_W   = (const float*)d_in[2];
    const float* mlp_b   = (const float*)d_in[3];
    const float* mlp_g   = (const float*)d_in[4];
    const float* mlp_be  = (const float*)d_in[5];
    const float* bn0_g   = (const float*)d_in[6];
    const float* bn0_be  = (const float*)d_in[7];
    const float* cls_W   = (const float*)d_in[8];
    const float* cls_b   = (const float*)d_in[9];
    const float* Wg[2]    = {(const float*)d_in[10], (const float*)d_in[19]};
    const float* Wh[2]    = {(const float*)d_in[11], (const float*)d_in[20]};
    const float* bh[2]    = {(const float*)d_in[12], (const float*)d_in[21]};
    const float* Wcon[2]  = {(const float*)d_in[13], (const float*)d_in[22]};
    const float* Wdis[2]  = {(const float*)d_in[14], (const float*)d_in[23]};
    const float* Wself[2] = {(const float*)d_in[15], (const float*)d_in[24]};
    const float* bself[2] = {(const float*)d_in[16], (const float*)d_in[25]};
    const float* Wgate[2] = {(const float*)d_in[17], (const float*)d_in[26]};
    const float* bgate[2] = {(const float*)d_in[18], (const float*)d_in[27]};
    const int* ei0 = ei;
    const int* ei1 = ei + N_EDGES;
    float* out = (float*)d_out;

    float *pH0, *pX1, *pTmp, *pG, *pS, *pZ, *pStats;
    int *pOff, *pCur, *pCnt, *pEid;
    cudaGetSymbolAddress((void**)&pH0,   d_h0);
    cudaGetSymbolAddress((void**)&pX1,   d_x1);
    cudaGetSymbolAddress((void**)&pTmp,  d_tmp);
    cudaGetSymbolAddress((void**)&pG,    d_G);
    cudaGetSymbolAddress((void**)&pS,    d_s);
    cudaGetSymbolAddress((void**)&pZ,    d_Z);
    cudaGetSymbolAddress((void**)&pStats,d_stats);
    cudaGetSymbolAddress((void**)&pOff,  d_off);
    cudaGetSymbolAddress((void**)&pCur,  d_cur);
    cudaGetSymbolAddress((void**)&pCnt,  d_cnt);
    cudaGetSymbolAddress((void**)&pEid,  d_eid);

    const int GR = (N_NODES + 127) / 128;          // 391 row blocks

    // ---- MLP + BN + relu -> h0
    {
        GemmParts gp = {};
        gp.B[0] = mlp_W; gp.bias[0] = mlp_b; gp.ncols[0] = 128;
        gemm_nt<<<dim3(GR, 1), 256>>>(x, N_NODES, gp, pTmp, 128);
    }
    zero_f<<<1, 256>>>(pStats, 256);
    bn_stats<<<(N_NODES + 255) / 256, 128>>>(pTmp, pStats);
    bn_apply<<<(N_NODES * 32 + 255) / 256, 256>>>((const float4*)pTmp, pStats,
                                                  mlp_g, mlp_be, nullptr,
                                                  (float4*)pH0);

    // ---- CSR by col (shared by both layers)
    init_counts_k<<<(N_NODES + 255) / 256, 256>>>(pCnt);
    hist_k<<<(N_EDGES + 255) / 256, 256>>>(ei1, pCnt);
    scan_k<<<1, 1024>>>(pCnt, pOff, pCur);
    csr_fill_k<<<(EAUG + 255) / 256, 256>>>(ei1, pCur, pEid);

    // ---- conv layers
    const float* lin[2] = {pH0, pX1};
    for (int l = 0; l < 2; l++) {
        GemmParts gp = {};
        gp.B[0] = Wg[l];   gp.ncols[0] = 128;
        gp.B[1] = Wcon[l]; gp.ncols[1] = 128;
        gp.B[2] = Wdis[l]; gp.ncols[2] = 128;
        gp.B[3] = Wself[l]; gp.bias[3] = bself[l]; gp.ncols[3] = 128;
        gemm_nt<<<dim3(GR, 4), 256>>>(lin[l], N_NODES, gp, pG, 512);

        zero_f<<<(2 * N_NODES + 255) / 256, 256>>>(pZ, 2 * N_NODES);
        edge_pass1<<<(EAUG * 32 + 255) / 256, 256>>>(pG, ei0, ei1, Wh[l], bh[l],
                                                     pS, pZ);
        recip_f<<<(2 * N_NODES + 255) / 256, 256>>>(pZ, 2 * N_NODES);
        agg_gate<<<(N_NODES * 32 + 255) / 256, 256>>>(pG, pOff, pEid, ei0, pS, pZ,
                                                      Wgate[l], bgate[l],
                                                      (l == 0) ? nullptr : pX1,
                                                      pTmp);
        if (l == 0) {
            zero_f<<<1, 256>>>(pStats, 256);
            bn_stats<<<(N_NODES + 255) / 256, 128>>>(pTmp, pStats);
            bn_apply<<<(N_NODES * 32 + 255) / 256, 256>>>((const float4*)pTmp,
                                                          pStats, bn0_g, bn0_be,
                                                          (const float4*)pH0,
                                                          (float4*)pX1);
        }
    }

    // ---- classifier: out = x2 @ cls_W.T + cls_b   (x2 lives in d_tmp)
    {
        GemmParts gp = {};
        gp.B[0] = cls_W; gp.bias[0] = cls_b; gp.ncols[0] = 40;
        gemm_nt<<<dim3(GR, 1), 256>>>(pTmp, N_NODES, gp, out, 40);
    }
}